// round 11
// baseline (speedup 1.0000x reference)
#include <cuda_runtime.h>
#include <cuda_bf16.h>
#include <math.h>

// Problem constants (fixed by the reference)
#define BSZ     16
#define DIM     4096
#define NH      32
#define NKV     8
#define HD      128
#define SEQ     4096
#define POS     4095
#define NCHUNK  8
#define CHUNK   512   // SEQ / NCHUNK
#define SUBK    64    // keys per staged sub-tile
#define NSUB    (CHUNK / SUBK)   // 8
#define KROW    128   // floats per K/V row (unpadded: LDS.128 phases align with rows)
#define TILEF   (SUBK * KROW)    // floats per tile (32 KB)

#define KVROWS  (NKV * HD)       // 1024 rows in wk / wv

// GEMM tiling
#define KC2     128
#define NK2     (DIM / KC2)      // 32
#define GROWS   16               // rows per GEMM block

// ---------------- scratch (static __device__, no allocation) ----------------
__device__ float g_xt2[8 * DIM * 2];                    // x pair-major [pair][d][2]
__device__ float g_q[BSZ * NH * HD];                    // [b][h][d]  (rope+scale applied)
__device__ float g_k[BSZ * KVROWS];                     // [b][kvh][d] (rope applied)
__device__ float g_v[BSZ * KVROWS];                     // [b][kvh][d]
__device__ float g_at2[8 * DIM * 2];                    // attn out pair-major [pair][e][2]
__device__ float g_Opart[BSZ * NKV * NCHUNK * 4 * HD];  // [b][kvh][chunk][hloc][d]
__device__ float g_l[BSZ * NKV * NCHUNK * 4];

// ---------------- f32x2 helpers (sm_103a packed fp32) ----------------
__device__ __forceinline__ unsigned long long pack2(float a, float b) {
    unsigned long long r;
    asm("mov.b64 %0, {%1, %2};" : "=l"(r) : "f"(a), "f"(b));
    return r;
}
__device__ __forceinline__ void unpack2(unsigned long long v, float& a, float& b) {
    asm("mov.b64 {%0, %1}, %2;" : "=f"(a), "=f"(b) : "l"(v));
}
__device__ __forceinline__ unsigned long long fma2(unsigned long long a,
                                                   unsigned long long b,
                                                   unsigned long long c) {
    unsigned long long d;
    asm("fma.rn.f32x2 %0, %1, %2, %3;" : "=l"(d) : "l"(a), "l"(b), "l"(c));
    return d;
}
__device__ __forceinline__ unsigned long long add2(unsigned long long a,
                                                   unsigned long long b) {
    unsigned long long d;
    asm("add.rn.f32x2 %0, %1, %2;" : "=l"(d) : "l"(a), "l"(b));
    return d;
}

// ---------------- cp.async helpers ----------------
__device__ __forceinline__ void cp_async16(void* smem, const void* gmem) {
    unsigned sa = (unsigned)__cvta_generic_to_shared(smem);
    asm volatile("cp.async.ca.shared.global [%0], [%1], 16;" :: "r"(sa), "l"(gmem) : "memory");
}
__device__ __forceinline__ void cp_commit() {
    asm volatile("cp.async.commit_group;" ::: "memory");
}
__device__ __forceinline__ void cp_wait2() {
    asm volatile("cp.async.wait_group 2;" ::: "memory");
}
__device__ __forceinline__ void cp_wait1() {
    asm volatile("cp.async.wait_group 1;" ::: "memory");
}
__device__ __forceinline__ void cp_wait0() {
    asm volatile("cp.async.wait_group 0;" ::: "memory");
}

// ---------------- x transpose: x[b][d] -> g_xt2 pair-major ----------------
__global__ void __launch_bounds__(256) transpose_x_kernel(const float* __restrict__ x)
{
    int gid = blockIdx.x * 256 + threadIdx.x;   // gid = b*4096 + d
    int b = gid >> 12;
    int d = gid & 4095;
    g_xt2[(b >> 1) * (DIM * 2) + d * 2 + (b & 1)] = x[gid];
}

// ---------------- GEMM core (16-row tiles, 3-stage cp.async, f32x2) ----------------
// mode: 0 = rope + 1/sqrt(HD) scale (q), 1 = rope (k), 2 = plain (v / wo)
__device__ __forceinline__ void gemm_core(const float* __restrict__ Wblk,
                                          const float* __restrict__ xt2,
                                          float* __restrict__ dst,
                                          int dsz, int drow0, int mode,
                                          const float* __restrict__ fc,
                                          const float* __restrict__ fs)
{
    __shared__ __align__(16) float ws[3][GROWS][KC2];   // 24 KB
    __shared__ __align__(16) float xs[3][8][KC2][2];    // 24 KB

    const int tid  = threadIdx.x;
    const int warp = tid >> 5;
    const int lane = tid & 31;

    unsigned long long acc[16];
    #pragma unroll
    for (int i = 0; i < 16; i++) acc[i] = 0ULL;

    auto stage = [&](int c, int bufi) {
        #pragma unroll
        for (int j = 0; j < 2; j++) {           // W: 16 rows x 32 float4
            int idx = tid + j * 256;
            int row = idx >> 5, f4 = idx & 31;
            cp_async16(&ws[bufi][row][f4 * 4],
                       Wblk + (size_t)row * DIM + c * KC2 + f4 * 4);
        }
        #pragma unroll
        for (int j = 0; j < 2; j++) {           // x: 8 planes x 64 float4
            int idx = tid + j * 256;
            int p = idx >> 6, f4 = idx & 63;
            cp_async16(&xs[bufi][p][0][0] + f4 * 4,
                       xt2 + p * (DIM * 2) + c * (KC2 * 2) + f4 * 4);
        }
        cp_commit();
    };

    stage(0, 0);
    stage(1, 1);
    stage(2, 2);

    for (int c = 0; c < NK2; c++) {
        int rem = NK2 - 1 - c;
        if (rem >= 2) cp_wait2(); else if (rem == 1) cp_wait1(); else cp_wait0();
        __syncthreads();
        const int cb = c % 3;

        #pragma unroll
        for (int s = 0; s < KC2 / 32; s++) {
            int kl = s * 32 + lane;
            float w0 = ws[cb][warp * 2 + 0][kl];
            float w1 = ws[cb][warp * 2 + 1][kl];

            unsigned long long xp[8];
            #pragma unroll
            for (int p = 0; p < 8; p++)
                xp[p] = *reinterpret_cast<const unsigned long long*>(&xs[cb][p][kl][0]);

            unsigned long long wv;
            wv = pack2(w0, w0);
            #pragma unroll
            for (int p = 0; p < 8; p++) acc[0 * 8 + p] = fma2(wv, xp[p], acc[0 * 8 + p]);
            wv = pack2(w1, w1);
            #pragma unroll
            for (int p = 0; p < 8; p++) acc[1 * 8 + p] = fma2(wv, xp[p], acc[1 * 8 + p]);
        }
        __syncthreads();
        if (c + 3 < NK2) stage(c + 3, cb);
    }

    // butterfly reduce across lanes (k partials)
    #pragma unroll
    for (int off = 16; off; off >>= 1) {
        #pragma unroll
        for (int i = 0; i < 16; i++)
            acc[i] = add2(acc[i], __shfl_xor_sync(0xffffffffu, acc[i], off));
    }

    if (lane < 16) {
        int p = lane >> 1, h = lane & 1;
        int row = drow0 + warp * 2;            // even row of the pair
        float lo0, hi0, lo1, hi1;
        unpack2(acc[0 * 8 + p], lo0, hi0);     // even row value
        unpack2(acc[1 * 8 + p], lo1, hi1);     // odd row value
        float ve = h ? hi0 : lo0;
        float vo = h ? hi1 : lo1;
        if (mode < 2) {                        // rope pair (ve, vo)
            int i = (row & 127) >> 1;
            float c = fc[i], s = fs[i];
            float e = ve * c - vo * s;
            float o = ve * s + vo * c;
            if (mode == 0) {
                const float scale = 0.08838834764831845f;   // 1/sqrt(128)
                e *= scale; o *= scale;
            }
            ve = e; vo = o;
        }
        dst[(size_t)lane * dsz + row]     = ve;
        dst[(size_t)lane * dsz + row + 1] = vo;
    }
}

// Fused QKV GEMM over 6144 rows (384 blocks x 16 rows), rope fused
__global__ void __launch_bounds__(256) qkv_gemm_kernel(const float* __restrict__ wq,
                                                       const float* __restrict__ wk,
                                                       const float* __restrict__ wv,
                                                       const float* __restrict__ fc,
                                                       const float* __restrict__ fs)
{
    int row0 = blockIdx.x * GROWS;
    const float* Wblk; float* dst; int dsz, drow0, mode;
    if (row0 < 4096) {
        Wblk = wq + (size_t)row0 * DIM;          dst = g_q; dsz = 4096;   drow0 = row0;          mode = 0;
    } else if (row0 < 4096 + KVROWS) {
        Wblk = wk + (size_t)(row0 - 4096) * DIM; dst = g_k; dsz = KVROWS; drow0 = row0 - 4096;   mode = 1;
    } else {
        Wblk = wv + (size_t)(row0 - 4096 - KVROWS) * DIM;
        dst = g_v; dsz = KVROWS; drow0 = row0 - 4096 - KVROWS; mode = 2;
    }
    gemm_core(Wblk, g_xt2, dst, dsz, drow0, mode, fc, fs);
}

__global__ void __launch_bounds__(256) wo_gemm_kernel(const float* __restrict__ wo,
                                                      float* __restrict__ out)
{
    int row0 = blockIdx.x * GROWS;
    gemm_core(wo + (size_t)row0 * DIM, g_at2, out, 4096, row0, 2, nullptr, nullptr);
}

// ---------------- two-phase flash-decoding partial attention ----------------
// grid (chunk=8, kvh=8, b=16), 256 threads = 8 warps, 3 blocks/SM.
// Phase 1: stream K (double-buffered 64-key tiles), q in registers,
//          scores -> exp inline -> sc, l in registers (no max; scores small).
// Phase 2: stream V; warp = 8 keys, lane = 4-dim slice, all 4 heads per lane
//          (each V row read once from smem).
__global__ void __launch_bounds__(256, 3) attn_partial_kernel(const float* __restrict__ cache_k,
                                                              const float* __restrict__ cache_v)
{
    extern __shared__ __align__(16) float dyn[];        // ring[2][SUBK][KROW] = 64 KB

    __shared__ __align__(16) float sc[CHUNK][4];        // 8 KB (p values, float4 rows)
    __shared__ float redl[8][4];
    __shared__ float lfin[4];

    const int chunk = blockIdx.x;
    const int kvh   = blockIdx.y;
    const int b     = blockIdx.z;
    const int tid   = threadIdx.x;
    const int warp  = tid >> 5;
    const int lane  = tid & 31;
    const int g     = lane >> 3;     // key within warp's group of 4
    const int s     = lane & 7;      // dim slice (16B units)

    const size_t rowstride = (size_t)NKV * HD;
    const float* kbase = cache_k + ((size_t)b * SEQ + (size_t)chunk * CHUNK) * rowstride
                         + (size_t)kvh * HD;
    const float* vbase = cache_v + ((size_t)b * SEQ + (size_t)chunk * CHUNK) * rowstride
                         + (size_t)kvh * HD;

    // q in registers: head h, slice dims 4*(s+8j)..+3
    ulonglong2 qr[4][4];
    #pragma unroll
    for (int h = 0; h < 4; h++) {
        const float* qp = &g_q[((b * NH) + kvh * 4 + h) * HD];
        #pragma unroll
        for (int j = 0; j < 4; j++)
            qr[h][j] = *reinterpret_cast<const ulonglong2*>(&qp[4 * (s + 8 * j)]);
    }

    auto stage = [&](const float* src, int t, int bufi) {
        const float* stile = src + (size_t)(t * SUBK) * rowstride;
        float* dstb = dyn + bufi * TILEF;
        #pragma unroll
        for (int j = 0; j < 8; j++) {          // 64 rows x 32 float4
            int idx = tid + j * 256;
            int row = idx >> 5, f4 = idx & 31;
            cp_async16(dstb + row * KROW + f4 * 4,
                       stile + (size_t)row * rowstride + f4 * 4);
        }
        cp_commit();
    };

    const bool dofix = (chunk == NCHUNK - 1);
    float lacc = 0.f;

    // ================= phase 1: K stream, scores -> exp -> sc =================
    stage(kbase, 0, 0);
    stage(kbase, 1, 1);

    for (int t = 0; t < NSUB; t++) {
        if (t < NSUB - 1) cp_wait1(); else cp_wait0();
        __syncthreads();
        float* kbuf = dyn + (t & 1) * TILEF;

        if (dofix && t == NSUB - 1) {       // substitute key POS with rope'd k
            if (warp == 0)
                reinterpret_cast<float4*>(kbuf + (SUBK - 1) * KROW)[lane] =
                    reinterpret_cast<const float4*>(&g_k[(b * NKV + kvh) * HD])[lane];
            __syncthreads();
        }

        #pragma unroll
        for (int it = 0; it < 2; it++) {
            int klocal = warp * 8 + it * 4 + g;
            const ulonglong2* krow =
                reinterpret_cast<const ulonglong2*>(kbuf + klocal * KROW);
            ulonglong2 k0 = krow[s];
            ulonglong2 k1 = krow[s + 8];
            ulonglong2 k2 = krow[s + 16];
            ulonglong2 k3 = krow[s + 24];

            #pragma unroll
            for (int h = 0; h < 4; h++) {
                unsigned long long a = fma2(qr[h][0].x, k0.x, 0ULL);
                a = fma2(qr[h][0].y, k0.y, a);
                a = fma2(qr[h][1].x, k1.x, a);
                a = fma2(qr[h][1].y, k1.y, a);
                a = fma2(qr[h][2].x, k2.x, a);
                a = fma2(qr[h][2].y, k2.y, a);
                a = fma2(qr[h][3].x, k3.x, a);
                a = fma2(qr[h][3].y, k3.y, a);
                float lo, hi; unpack2(a, lo, hi);
                float sum = lo + hi;
                sum += __shfl_xor_sync(0xffffffffu, sum, 1);
                sum += __shfl_xor_sync(0xffffffffu, sum, 2);
                sum += __shfl_xor_sync(0xffffffffu, sum, 4);
                if (s == h) {
                    float pe = __expf(sum);
                    sc[t * SUBK + klocal][h] = pe;
                    lacc += pe;
                }
            }
        }
        __syncthreads();
        if (t + 2 < NSUB) stage(kbase, t + 2, t & 1);
    }

    // ================= V prologue (covers l-reduce) =================
    stage(vbase, 0, 0);
    stage(vbase, 1, 1);

    // l reduction: lacc valid on lanes where s<4 (head=s), summed over g groups
    lacc += __shfl_xor_sync(0xffffffffu, lacc, 8);
    lacc += __shfl_xor_sync(0xffffffffu, lacc, 16);
    if (lane < 4) redl[warp][lane] = lacc;
    __syncthreads();
    if (tid < 4) {
        float l = 0.f;
        #pragma unroll
        for (int w = 0; w < 8; w++) l += redl[w][tid];
        lfin[tid] = l;
    }

    // ================= phase 2: V stream, P @ V =================
    // warp owns keys warp*8..warp*8+7 per tile; lane = 4-float dim slice;
    // all 4 heads accumulated per lane.
    unsigned long long vacc[4][2];
    #pragma unroll
    for (int h = 0; h < 4; h++) { vacc[h][0] = 0ULL; vacc[h][1] = 0ULL; }

    for (int t = 0; t < NSUB; t++) {
        if (t < NSUB - 1) cp_wait1(); else cp_wait0();
        __syncthreads();
        float* vbuf = dyn + (t & 1) * TILEF;

        if (dofix && t == NSUB - 1) {       // substitute value POS with new v
            if (warp == 0)
                reinterpret_cast<float4*>(vbuf + (SUBK - 1) * KROW)[lane] =
                    reinterpret_cast<const float4*>(&g_v[(b * NKV + kvh) * HD])[lane];
            __syncthreads();
        }

        #pragma unroll
        for (int kk = 0; kk < 8; kk++) {
            int kl = warp * 8 + kk;
            ulonglong2 vv = reinterpret_cast<const ulonglong2*>(vbuf + kl * KROW)[lane];
            float4 pr = *reinterpret_cast<const float4*>(&sc[t * SUBK + kl][0]);
            unsigned long long pp;
            pp = pack2(pr.x, pr.x);
            vacc[0][0] = fma2(pp, vv.x, vacc[0][0]);
            vacc[0][1] = fma2(pp, vv.y, vacc[0][1]);
            pp = pack2(pr.y, pr.y);
            vacc[1][0] = fma2(pp, vv.x, vacc[1][0]);
            vacc[1][1] = fma2(pp, vv.y, vacc[1][1]);
            pp = pack2(pr.z, pr.z);
            vacc[2][0] = fma2(pp, vv.x, vacc[2][0]);
            vacc[2][1] = fma2(pp, vv.y, vacc[2][1]);
            pp = pack2(pr.w, pr.w);
            vacc[3][0] = fma2(pp, vv.x, vacc[3][0]);
            vacc[3][1] = fma2(pp, vv.y, vacc[3][1]);
        }
        __syncthreads();
        if (t + 2 < NSUB) stage(vbase, t + 2, t & 1);
    }

    // ---- epilogue: per-warp partial O -> smem (alias ring buffer) -> reduce ----
    float* ored = dyn;                  // [8 warps][4 heads][HD] = 16 KB
    __syncthreads();
    #pragma unroll
    for (int h = 0; h < 4; h++) {
        float o0, o1, o2, o3;
        unpack2(vacc[h][0], o0, o1);
        unpack2(vacc[h][1], o2, o3);
        reinterpret_cast<float4*>(&ored[(warp * 4 + h) * HD])[lane] =
            make_float4(o0, o1, o2, o3);
    }
    __syncthreads();

    int pbase = ((b * NKV + kvh) * NCHUNK + chunk) * 4;
    #pragma unroll
    for (int r = 0; r < 2; r++) {
        int idx = tid + r * 256;
        int h = idx >> 7, d = idx & 127;
        float sum = 0.f;
        #pragma unroll
        for (int w = 0; w < 8; w++)
            sum += ored[(w * 4 + h) * HD + d];
        g_Opart[(size_t)(pbase + h) * HD + d] = sum;
    }
    if (tid < 4) g_l[pbase + tid] = lfin[tid];
}

// ---------------- combine (no max needed) -> g_at2 (pair-major) ----------------
__global__ void __launch_bounds__(128) combine_kernel()
{
    int kvh = blockIdx.x;
    int b   = blockIdx.y;
    int d   = threadIdx.x;

    #pragma unroll
    for (int h = 0; h < 4; h++) {
        int base = ((b * NKV + kvh) * NCHUNK) * 4 + h;   // + c*4
        float num = 0.f, den = 0.f;
        #pragma unroll
        for (int c = 0; c < NCHUNK; c++) {
            den += g_l[base + c * 4];
            num += g_Opart[(size_t)(base + c * 4) * HD + d];
        }
        int e = (kvh * 4 + h) * HD + d;
        g_at2[(b >> 1) * (DIM * 2) + e * 2 + (b & 1)] = num / den;
    }
}

// ---------------- launcher ----------------
#define ATTN_SMEM (2 * TILEF * (int)sizeof(float))   // 65536 B dynamic

extern "C" void kernel_launch(void* const* d_in, const int* in_sizes, int n_in,
                              void* d_out, int out_size)
{
    (void)in_sizes; (void)n_in; (void)out_size;
    const float* x  = (const float*)d_in[0];
    const float* wq = (const float*)d_in[1];
    const float* wk = (const float*)d_in[2];
    const float* wv = (const float*)d_in[3];
    const float* wo = (const float*)d_in[4];
    const float* ck = (const float*)d_in[5];
    const float* cv = (const float*)d_in[6];
    const float* fc = (const float*)d_in[7];
    const float* fs = (const float*)d_in[8];
    float* out = (float*)d_out;

    cudaFuncSetAttribute(attn_partial_kernel,
                         cudaFuncAttributeMaxDynamicSharedMemorySize, ATTN_SMEM);

    transpose_x_kernel<<<256, 256>>>(x);
    qkv_gemm_kernel<<<384, 256>>>(wq, wk, wv, fc, fs);
    attn_partial_kernel<<<dim3(NCHUNK, NKV, BSZ), 256, ATTN_SMEM>>>(ck, cv);
    combine_kernel<<<dim3(NKV, BSZ), 128>>>();
    wo_gemm_kernel<<<256, 256>>>(wo, out);
}

// round 13
// speedup vs baseline: 1.3960x; 1.3960x over previous
#include <cuda_runtime.h>
#include <cuda_bf16.h>
#include <math.h>

// Problem constants (fixed by the reference)
#define BSZ     16
#define DIM     4096
#define NH      32
#define NKV     8
#define HD      128
#define SEQ     4096
#define POS     4095
#define NCHUNK  8
#define CHUNK   512   // SEQ / NCHUNK
#define SUBK    64    // keys per staged sub-tile
#define NSUB    (CHUNK / SUBK)   // 8
#define KROW    132   // padded floats per K/V row (33 float4, 16B aligned)
#define TILEF   (SUBK * KROW)

#define KVROWS  (NKV * HD)       // 1024 rows in wk / wv

// GEMM tiling
#define KC2     128
#define NK2     (DIM / KC2)      // 32
#define GROWS   16               // rows per GEMM block

// ---------------- scratch (static __device__, no allocation) ----------------
__device__ float g_xt2[8 * DIM * 2];                    // x pair-major [pair][d][2]
__device__ float g_q[BSZ * NH * HD];                    // [b][h][d]
__device__ float g_k[BSZ * KVROWS];                     // [b][kvh][d]
__device__ float g_v[BSZ * KVROWS];                     // [b][kvh][d]
__device__ float g_at2[8 * DIM * 2];                    // attn out pair-major [pair][e][2]
__device__ float g_Opart[BSZ * NKV * NCHUNK * 4 * HD];  // [b][kvh][chunk][hloc][d]
__device__ float g_l[BSZ * NKV * NCHUNK * 4];

// ---------------- f32x2 helpers (sm_103a packed fp32) ----------------
__device__ __forceinline__ unsigned long long pack2(float a, float b) {
    unsigned long long r;
    asm("mov.b64 %0, {%1, %2};" : "=l"(r) : "f"(a), "f"(b));
    return r;
}
__device__ __forceinline__ void unpack2(unsigned long long v, float& a, float& b) {
    asm("mov.b64 {%0, %1}, %2;" : "=f"(a), "=f"(b) : "l"(v));
}
__device__ __forceinline__ unsigned long long fma2(unsigned long long a,
                                                   unsigned long long b,
                                                   unsigned long long c) {
    unsigned long long d;
    asm("fma.rn.f32x2 %0, %1, %2, %3;" : "=l"(d) : "l"(a), "l"(b), "l"(c));
    return d;
}
__device__ __forceinline__ unsigned long long add2(unsigned long long a,
                                                   unsigned long long b) {
    unsigned long long d;
    asm("add.rn.f32x2 %0, %1, %2;" : "=l"(d) : "l"(a), "l"(b));
    return d;
}

// ---------------- cp.async helpers ----------------
__device__ __forceinline__ void cp_async16(void* smem, const void* gmem) {
    unsigned sa = (unsigned)__cvta_generic_to_shared(smem);
    asm volatile("cp.async.ca.shared.global [%0], [%1], 16;" :: "r"(sa), "l"(gmem) : "memory");
}
__device__ __forceinline__ void cp_commit() {
    asm volatile("cp.async.commit_group;" ::: "memory");
}
__device__ __forceinline__ void cp_wait2() {
    asm volatile("cp.async.wait_group 2;" ::: "memory");
}
__device__ __forceinline__ void cp_wait1() {
    asm volatile("cp.async.wait_group 1;" ::: "memory");
}
__device__ __forceinline__ void cp_wait0() {
    asm volatile("cp.async.wait_group 0;" ::: "memory");
}

// ---------------- x transpose: x[b][d] -> g_xt2 pair-major ----------------
__global__ void __launch_bounds__(256) transpose_x_kernel(const float* __restrict__ x)
{
    int gid = blockIdx.x * 256 + threadIdx.x;   // gid = b*4096 + d
    int b = gid >> 12;
    int d = gid & 4095;
    g_xt2[(b >> 1) * (DIM * 2) + d * 2 + (b & 1)] = x[gid];
}

// ---------------- GEMM core (16-row tiles, 3-stage cp.async, f32x2) ----------------
__device__ __forceinline__ void gemm_core(const float* __restrict__ Wblk,
                                          const float* __restrict__ xt2,
                                          float* __restrict__ dst,
                                          int dsz, int drow0)
{
    __shared__ __align__(16) float ws[3][GROWS][KC2];   // 24 KB
    __shared__ __align__(16) float xs[3][8][KC2][2];    // 24 KB

    const int tid  = threadIdx.x;
    const int warp = tid >> 5;
    const int lane = tid & 31;

    unsigned long long acc[16];
    #pragma unroll
    for (int i = 0; i < 16; i++) acc[i] = 0ULL;

    auto stage = [&](int c, int bufi) {
        #pragma unroll
        for (int j = 0; j < 2; j++) {           // W: 16 rows x 32 float4
            int idx = tid + j * 256;
            int row = idx >> 5, f4 = idx & 31;
            cp_async16(&ws[bufi][row][f4 * 4],
                       Wblk + (size_t)row * DIM + c * KC2 + f4 * 4);
        }
        #pragma unroll
        for (int j = 0; j < 2; j++) {           // x: 8 planes x 64 float4
            int idx = tid + j * 256;
            int p = idx >> 6, f4 = idx & 63;
            cp_async16(&xs[bufi][p][0][0] + f4 * 4,
                       xt2 + p * (DIM * 2) + c * (KC2 * 2) + f4 * 4);
        }
        cp_commit();
    };

    stage(0, 0);
    stage(1, 1);
    stage(2, 2);

    for (int c = 0; c < NK2; c++) {
        int rem = NK2 - 1 - c;
        if (rem >= 2) cp_wait2(); else if (rem == 1) cp_wait1(); else cp_wait0();
        __syncthreads();
        const int cb = c % 3;

        #pragma unroll
        for (int s = 0; s < KC2 / 32; s++) {
            int kl = s * 32 + lane;
            float w0 = ws[cb][warp * 2 + 0][kl];
            float w1 = ws[cb][warp * 2 + 1][kl];

            unsigned long long xp[8];
            #pragma unroll
            for (int p = 0; p < 8; p++)
                xp[p] = *reinterpret_cast<const unsigned long long*>(&xs[cb][p][kl][0]);

            unsigned long long wv;
            wv = pack2(w0, w0);
            #pragma unroll
            for (int p = 0; p < 8; p++) acc[0 * 8 + p] = fma2(wv, xp[p], acc[0 * 8 + p]);
            wv = pack2(w1, w1);
            #pragma unroll
            for (int p = 0; p < 8; p++) acc[1 * 8 + p] = fma2(wv, xp[p], acc[1 * 8 + p]);
        }
        __syncthreads();
        if (c + 3 < NK2) stage(c + 3, cb);
    }

    // butterfly reduce across lanes (k partials)
    #pragma unroll
    for (int off = 16; off; off >>= 1) {
        #pragma unroll
        for (int i = 0; i < 16; i++)
            acc[i] = add2(acc[i], __shfl_xor_sync(0xffffffffu, acc[i], off));
    }

    if (lane < 16) {
        int p = lane >> 1, h = lane & 1;
        #pragma unroll
        for (int r = 0; r < 2; r++) {
            float lo, hi;
            unpack2(acc[r * 8 + p], lo, hi);
            dst[(size_t)lane * dsz + drow0 + warp * 2 + r] = h ? hi : lo;
        }
    }
}

// Fused QKV GEMM over 6144 rows (384 blocks x 16 rows)
__global__ void __launch_bounds__(256) qkv_gemm_kernel(const float* __restrict__ wq,
                                                       const float* __restrict__ wk,
                                                       const float* __restrict__ wv)
{
    int row0 = blockIdx.x * GROWS;
    const float* Wblk; float* dst; int dsz, drow0;
    if (row0 < 4096) {
        Wblk = wq + (size_t)row0 * DIM;          dst = g_q; dsz = 4096;   drow0 = row0;
    } else if (row0 < 4096 + KVROWS) {
        Wblk = wk + (size_t)(row0 - 4096) * DIM; dst = g_k; dsz = KVROWS; drow0 = row0 - 4096;
    } else {
        Wblk = wv + (size_t)(row0 - 4096 - KVROWS) * DIM;
        dst = g_v; dsz = KVROWS; drow0 = row0 - 4096 - KVROWS;
    }
    gemm_core(Wblk, g_xt2, dst, dsz, drow0);
}

__global__ void __launch_bounds__(256) wo_gemm_kernel(const float* __restrict__ wo,
                                                      float* __restrict__ out)
{
    int row0 = blockIdx.x * GROWS;
    gemm_core(wo + (size_t)row0 * DIM, g_at2, out, 4096, row0);
}

// ---------------- RoPE (+ 1/sqrt(HD) scale folded into q) ----------------
__global__ void __launch_bounds__(256) rope_kernel(const float* __restrict__ fcos,
                                                   const float* __restrict__ fsin)
{
    int id = blockIdx.x * 256 + threadIdx.x;
    const float scale = 0.08838834764831845f;   // 1/sqrt(128)
    if (id < BSZ * NH * (HD / 2)) {
        int i = id & 63;
        float c = fcos[i], s = fsin[i];
        float a  = g_q[2 * id];
        float bb = g_q[2 * id + 1];
        g_q[2 * id]     = (a * c - bb * s) * scale;
        g_q[2 * id + 1] = (a * s + bb * c) * scale;
    } else {
        int kid = id - BSZ * NH * (HD / 2);
        if (kid < BSZ * NKV * (HD / 2)) {
            int i = kid & 63;
            float c = fcos[i], s = fsin[i];
            float a  = g_k[2 * kid];
            float bb = g_k[2 * kid + 1];
            g_k[2 * kid]     = a * c - bb * s;
            g_k[2 * kid + 1] = a * s + bb * c;
        }
    }
}

// ---------------- two-phase flash-decoding partial attention ----------------
// Round-5 structure (measured 100us) + inline exp (no softmax bubble).
// grid (chunk=8, kvh=8, b=16), 256 threads = 8 warps, natural occupancy.
// Dynamic smem: kvbuf[2][SUBK][KROW] + sc[512][4] + ored[8][128]
__global__ void __launch_bounds__(256) attn_partial_kernel(const float* __restrict__ cache_k,
                                                           const float* __restrict__ cache_v)
{
    extern __shared__ __align__(16) float dyn[];
    float* kvbuf = dyn;                         // 2*64*132 = 16896 floats
    float* sc    = dyn + 2 * TILEF;             // 512*4 floats, [key][head]
    float* ored  = sc + CHUNK * 4;              // 8*128 floats

    __shared__ float redl[8][4], lfin[4];

    const int chunk = blockIdx.x;
    const int kvh   = blockIdx.y;
    const int b     = blockIdx.z;
    const int tid   = threadIdx.x;
    const int warp  = tid >> 5;
    const int lane  = tid & 31;
    const int g     = lane >> 3;     // key group within warp iter
    const int s     = lane & 7;      // dim slice

    const size_t rowstride = (size_t)NKV * HD;
    const float* kbase = cache_k + ((size_t)b * SEQ + (size_t)chunk * CHUNK) * rowstride
                         + (size_t)kvh * HD;
    const float* vbase = cache_v + ((size_t)b * SEQ + (size_t)chunk * CHUNK) * rowstride
                         + (size_t)kvh * HD;

    // q registers: head h, slice dims 4*(s+8j)..+3, packed f32x2 pairs
    ulonglong2 qr[4][4];
    #pragma unroll
    for (int h = 0; h < 4; h++) {
        const float* qp = &g_q[((b * NH) + kvh * 4 + h) * HD];
        #pragma unroll
        for (int j = 0; j < 4; j++)
            qr[h][j] = *reinterpret_cast<const ulonglong2*>(&qp[4 * (s + 8 * j)]);
    }

    auto stage = [&](const float* src, int t, int bufi) {
        const float* stile = src + (size_t)(t * SUBK) * rowstride;
        float* dstb = kvbuf + bufi * TILEF;
        #pragma unroll
        for (int j = 0; j < 8; j++) {      // 64 rows x 32 float4
            int idx = tid + j * 256;
            int row = idx >> 5, f4 = idx & 31;
            cp_async16(dstb + row * KROW + f4 * 4,
                       stile + (size_t)row * rowstride + f4 * 4);
        }
        cp_commit();
    };

    const bool dofix = (chunk == NCHUNK - 1);
    float lacc = 0.f;

    // ================= phase 1: QK scores -> exp inline -> sc =================
    stage(kbase, 0, 0);
    stage(kbase, 1, 1);

    for (int t = 0; t < NSUB; t++) {
        if (t < NSUB - 1) cp_wait1(); else cp_wait0();
        __syncthreads();
        float* buf = kvbuf + (t & 1) * TILEF;

        if (dofix && t == NSUB - 1) {       // substitute key POS with rope'd k
            if (warp == 0)
                reinterpret_cast<float4*>(buf + (SUBK - 1) * KROW)[lane] =
                    reinterpret_cast<const float4*>(&g_k[(b * NKV + kvh) * HD])[lane];
            __syncthreads();
        }

        #pragma unroll
        for (int it = 0; it < 2; it++) {
            int klocal = warp * 8 + it * 4 + g;
            const ulonglong2* krow = reinterpret_cast<const ulonglong2*>(buf + klocal * KROW);
            ulonglong2 k0 = krow[s];
            ulonglong2 k1 = krow[s + 8];
            ulonglong2 k2 = krow[s + 16];
            ulonglong2 k3 = krow[s + 24];

            #pragma unroll
            for (int h = 0; h < 4; h++) {
                unsigned long long a = fma2(qr[h][0].x, k0.x, 0ULL);
                a = fma2(qr[h][0].y, k0.y, a);
                a = fma2(qr[h][1].x, k1.x, a);
                a = fma2(qr[h][1].y, k1.y, a);
                a = fma2(qr[h][2].x, k2.x, a);
                a = fma2(qr[h][2].y, k2.y, a);
                a = fma2(qr[h][3].x, k3.x, a);
                a = fma2(qr[h][3].y, k3.y, a);
                float lo, hi; unpack2(a, lo, hi);
                float sum = lo + hi;
                sum += __shfl_xor_sync(0xffffffffu, sum, 1);
                sum += __shfl_xor_sync(0xffffffffu, sum, 2);
                sum += __shfl_xor_sync(0xffffffffu, sum, 4);
                if (s == h) {
                    float pe = __expf(sum);
                    sc[(t * SUBK + klocal) * 4 + h] = pe;
                    lacc += pe;
                }
            }
        }
        __syncthreads();
        if (t + 2 < NSUB) stage(kbase, t + 2, t & 1);
    }

    // ================= V prologue (covers l-reduce) =================
    stage(vbase, 0, 0);
    stage(vbase, 1, 1);

    // l reduction: lacc valid on lanes where s<4 (head=s); sum over g groups
    lacc += __shfl_xor_sync(0xffffffffu, lacc, 8);
    lacc += __shfl_xor_sync(0xffffffffu, lacc, 16);
    if (lane < 4) redl[warp][lane] = lacc;
    __syncthreads();
    if (tid < 4) {
        float l = 0.f;
        #pragma unroll
        for (int w = 0; w < 8; w++) l += redl[w][tid];
        lfin[tid] = l;
    }

    // ================= phase 2: P @ V =================
    const int vh    = warp & 3;      // head
    const int vhalf = warp >> 2;     // key half within sub-tile
    unsigned long long vacc0 = 0ULL, vacc1 = 0ULL;

    for (int t = 0; t < NSUB; t++) {
        if (t < NSUB - 1) cp_wait1(); else cp_wait0();
        __syncthreads();
        float* buf = kvbuf + (t & 1) * TILEF;

        if (dofix && t == NSUB - 1) {       // substitute value POS with new v
            if (warp == 0)
                reinterpret_cast<float4*>(buf + (SUBK - 1) * KROW)[lane] =
                    reinterpret_cast<const float4*>(&g_v[(b * NKV + kvh) * HD])[lane];
            __syncthreads();
        }

        #pragma unroll 4
        for (int kk = 0; kk < 32; kk++) {
            int kl = vhalf * 32 + kk;
            ulonglong2 vv = reinterpret_cast<const ulonglong2*>(buf + kl * KROW)[lane];
            float pv = sc[(t * SUBK + kl) * 4 + vh];
            unsigned long long pp = pack2(pv, pv);
            vacc0 = fma2(pp, vv.x, vacc0);
            vacc1 = fma2(pp, vv.y, vacc1);
        }
        __syncthreads();
        if (t + 2 < NSUB) stage(vbase, t + 2, t & 1);
    }

    // epilogue: combine key halves, write partials
    {
        float o0, o1, o2, o3;
        unpack2(vacc0, o0, o1);
        unpack2(vacc1, o2, o3);
        reinterpret_cast<float4*>(ored + (vhalf * 4 + vh) * HD)[lane] =
            make_float4(o0, o1, o2, o3);
    }
    __syncthreads();

    int pbase = ((b * NKV + kvh) * NCHUNK + chunk) * 4;
    #pragma unroll
    for (int r = 0; r < 2; r++) {
        int idx = tid + r * 256;
        int h = idx >> 7, d = idx & 127;
        g_Opart[(size_t)(pbase + h) * HD + d] = ored[h * HD + d] + ored[(4 + h) * HD + d];
    }
    if (tid < 4) g_l[pbase + tid] = lfin[tid];
}

// ---------------- combine (no max needed) -> g_at2 (pair-major) ----------------
__global__ void __launch_bounds__(128) combine_kernel()
{
    int kvh = blockIdx.x;
    int b   = blockIdx.y;
    int d   = threadIdx.x;

    #pragma unroll
    for (int h = 0; h < 4; h++) {
        int base = ((b * NKV + kvh) * NCHUNK) * 4 + h;   // + c*4
        float num = 0.f, den = 0.f;
        #pragma unroll
        for (int c = 0; c < NCHUNK; c++) {
            den += g_l[base + c * 4];
            num += g_Opart[(size_t)(base + c * 4) * HD + d];
        }
        int e = (kvh * 4 + h) * HD + d;
        g_at2[(b >> 1) * (DIM * 2) + e * 2 + (b & 1)] = num / den;
    }
}

// ---------------- launcher ----------------
#define ATTN_SMEM ((2 * TILEF + CHUNK * 4 + 8 * HD) * (int)sizeof(float))

extern "C" void kernel_launch(void* const* d_in, const int* in_sizes, int n_in,
                              void* d_out, int out_size)
{
    (void)in_sizes; (void)n_in; (void)out_size;
    const float* x  = (const float*)d_in[0];
    const float* wq = (const float*)d_in[1];
    const float* wk = (const float*)d_in[2];
    const float* wv = (const float*)d_in[3];
    const float* wo = (const float*)d_in[4];
    const float* ck = (const float*)d_in[5];
    const float* cv = (const float*)d_in[6];
    const float* fc = (const float*)d_in[7];
    const float* fs = (const float*)d_in[8];
    float* out = (float*)d_out;

    cudaFuncSetAttribute(attn_partial_kernel,
                         cudaFuncAttributeMaxDynamicSharedMemorySize, ATTN_SMEM);

    transpose_x_kernel<<<256, 256>>>(x);
    qkv_gemm_kernel<<<384, 256>>>(wq, wk, wv);
    rope_kernel<<<160, 256>>>(fc, fs);
    attn_partial_kernel<<<dim3(NCHUNK, NKV, BSZ), 256, ATTN_SMEM>>>(ck, cv);
    combine_kernel<<<dim3(NKV, BSZ), 128>>>();
    wo_gemm_kernel<<<256, 256>>>(wo, out);
}